// round 10
// baseline (speedup 1.0000x reference)
#include <cuda_runtime.h>
#include <cuda_bf16.h>
#include <cstdint>

// ---------------- problem constants ----------------
#define B_   1024
#define S_   336
#define C_   64
#define O_   168
#define T_   96
#define CH   64             // k per chunk
#define NCH  3
#define MT   128            // batches per GEMM tile
#define NTILES 512          // 64 channels x 8 b-tiles
#define GCTA  296           // persistent gemm CTAs (148 SMs x 2)
#define ROWB (O_ * 2)       // 336 bytes per (c,b) row in g_x

// ---------------- scratch (device globals; no allocs) ----------------
__device__ __nv_bfloat16 g_xhi[(size_t)C_ * B_ * O_];       // [c][b][o]
__device__ __nv_bfloat16 g_xlo[(size_t)C_ * B_ * O_];
__device__ unsigned char g_bhi[(size_t)C_ * NCH * T_ * 128];// pre-swizzled W hi image (padded)
__device__ unsigned char g_blo[(size_t)C_ * NCH * T_ * 128];
__device__ float         g_yT [(size_t)C_ * B_ * T_];       // [c][b][t]

// split f into bf16 hi + bf16 lo (pairwise, packed)
__device__ __forceinline__ void split2(float f0, float f1, uint32_t& h, uint32_t& l)
{
    __nv_bfloat162 hb = __floats2bfloat162_rn(f0, f1);
    float r0 = f0 - __bfloat162float(hb.x);
    float r1 = f1 - __bfloat162float(hb.y);
    __nv_bfloat162 lb = __floats2bfloat162_rn(r0, r1);
    h = *reinterpret_cast<uint32_t*>(&hb);
    l = *reinterpret_cast<uint32_t*>(&lb);
}
__device__ __forceinline__ uint32_t smem_u32(const void* p) {
    uint32_t a;
    asm("{ .reg .u64 t; cvta.to.shared.u64 t, %1; cvt.u32.u64 %0, t; }" : "=r"(a) : "l"(p));
    return a;
}
__device__ __forceinline__ void mma16816(float* d, const uint32_t* a, const uint32_t* b)
{
    asm volatile(
        "mma.sync.aligned.m16n8k16.row.col.f32.bf16.bf16.f32 "
        "{%0,%1,%2,%3}, {%4,%5,%6,%7}, {%8,%9}, {%0,%1,%2,%3};"
        : "+f"(d[0]), "+f"(d[1]), "+f"(d[2]), "+f"(d[3])
        : "r"(a[0]), "r"(a[1]), "r"(a[2]), "r"(a[3]), "r"(b[0]), "r"(b[1]));
}
__device__ __forceinline__ void ldsm4(uint32_t* r, uint32_t addr)
{
    asm volatile("ldmatrix.sync.aligned.m8n8.x4.shared.b16 {%0,%1,%2,%3}, [%4];"
                 : "=r"(r[0]), "=r"(r[1]), "=r"(r[2]), "=r"(r[3]) : "r"(addr));
}
#define CPA16(dst, src) \
    asm volatile("cp.async.cg.shared.global [%0], [%1], 16;" :: "r"(dst), "l"(src))
// cp.async with runtime src_size: bytes beyond src_size are zero-filled
#define CPA16Z(dst, src, n) \
    asm volatile("cp.async.cg.shared.global [%0], [%1], 16, %2;" :: "r"(dst), "l"(src), "r"(n))
#define CPA_COMMIT() asm volatile("cp.async.commit_group;" ::: "memory")
#define CPA_WAIT(n)  asm volatile("cp.async.wait_group %0;" :: "n"(n) : "memory")

// ================= T0: W[c][o][t] -> pre-swizzled bf16 hi/lo images (zero padded) =================
__global__ __launch_bounds__(256)
void t0_kernel(const float* __restrict__ W)
{
    const int c = blockIdx.x;
    const float* Wc = W + (size_t)c * (O_ * T_);
    for (int idx = threadIdx.x; idx < 48 * T_; idx += 256) {
        int oq = idx / T_;
        int t  = idx - oq * T_;
        int o  = oq * 4;
        float f0 = (o + 0 < O_) ? Wc[(o + 0) * T_ + t] : 0.f;
        float f1 = (o + 1 < O_) ? Wc[(o + 1) * T_ + t] : 0.f;
        float f2 = (o + 2 < O_) ? Wc[(o + 2) * T_ + t] : 0.f;
        float f3 = (o + 3 < O_) ? Wc[(o + 3) * T_ + t] : 0.f;
        uint2 hv, lv;
        split2(f0, f1, hv.x, lv.x);
        split2(f2, f3, hv.y, lv.y);
        int chunk = o >> 6;
        int kc    = o & 63;
        uint32_t off = (((uint32_t)(c * NCH + chunk) * T_ + t) << 7)
                     + (((uint32_t)(kc >> 3) ^ (t & 7)) << 4) + ((kc >> 2) & 1) * 8;
        *(uint2*)(g_bhi + off) = hv;
        *(uint2*)(g_blo + off) = lv;
    }
}

// ================= T1 (R5-proven): x[B,S,C] -> xT hi/lo [C,B,O_] =================
__global__ __launch_bounds__(256)
void t1_kernel(const float* __restrict__ x)
{
    __shared__ float smt[32 * 172];
    const int b    = blockIdx.x;
    const int half = blockIdx.y;
    const uint4* xb = reinterpret_cast<const uint4*>(
        x + (size_t)b * (S_ * C_) + (size_t)(S_ - O_) * C_);

    for (int i = threadIdx.x; i < O_ * 8; i += 256) {
        int o = i >> 3, q = i & 7;
        uint4 v = xb[o * 16 + half * 8 + q];
        float* d = &smt[(q * 4) * 172 + o];
        d[0 * 172] = __uint_as_float(v.x);
        d[1 * 172] = __uint_as_float(v.y);
        d[2 * 172] = __uint_as_float(v.z);
        d[3 * 172] = __uint_as_float(v.w);
    }
    __syncthreads();

    for (int idx = threadIdx.x; idx < 32 * 21; idx += 256) {
        int cl = idx / 21, ch = idx - cl * 21;
        const float* src = &smt[cl * 172 + ch * 8];
        float4 f0 = *(const float4*)(src);
        float4 f1 = *(const float4*)(src + 4);
        uint4 hw, lw;
        split2(f0.x, f0.y, hw.x, lw.x);
        split2(f0.z, f0.w, hw.y, lw.y);
        split2(f1.x, f1.y, hw.z, lw.z);
        split2(f1.z, f1.w, hw.w, lw.w);
        size_t base = ((size_t)(half * 32 + cl) * B_ + b) * O_ + ch * 8;
        *(uint4*)(g_xhi + base) = hw;
        *(uint4*)(g_xlo + base) = lw;
    }
}

// ================= GEMM: persistent CTAs, flattened (tile,chunk) cp.async pipeline =================
// stage layout (bytes): A_hi 16K | A_lo 16K | B_hi 12K | B_lo 12K  = 56K; 2 stages = 112K
#define OFF_AHI  0
#define OFF_ALO  16384
#define OFF_BHI  32768
#define OFF_BLO  45056
#define STG      57344
#define SMEM_TOT (2 * STG)

__device__ __forceinline__ void fill_chunk(uint32_t sbase, int c, int b0, int chunk, int tid)
{
    const char* axh = (const char*)g_xhi + (size_t)((c << 10) + b0) * ROWB;
    const char* axl = (const char*)g_xlo + (size_t)((c << 10) + b0) * ROWB;
    const int koff = chunk * 128;                      // byte offset of this chunk in a row
    #pragma unroll
    for (int it = 0; it < 4; it++) {
        int i = tid + it * 256;
        int r = i >> 3, cq = i & 7;
        int off   = koff + cq * 16;
        int avail = ROWB - off;
        avail = (avail < 0) ? 0 : ((avail > 16) ? 16 : avail);
        uint32_t sw = (uint32_t)r * 128 + (((uint32_t)cq ^ (r & 7)) << 4);
        size_t so = (size_t)r * ROWB + (avail ? off : 0);
        CPA16Z(sbase + OFF_AHI + sw, axh + so, avail);
        CPA16Z(sbase + OFF_ALO + sw, axl + so, avail);
    }
    const char* bh = (const char*)g_bhi + (size_t)(c * NCH + chunk) * (T_ * 128);
    const char* bl = (const char*)g_blo + (size_t)(c * NCH + chunk) * (T_ * 128);
    #pragma unroll
    for (int it = 0; it < 3; it++) {
        int i = tid + it * 256;
        CPA16(sbase + OFF_BHI + i * 16, bh + (size_t)i * 16);
        CPA16(sbase + OFF_BLO + i * 16, bl + (size_t)i * 16);
    }
}

__device__ __forceinline__ void mma_chunk(uint32_t base, int wm, int wn, int lane,
                                          float (*acc)[6][4])
{
    const int l7   = lane & 7;
    const int hi16 = lane >> 4;
    const int cbit = (lane >> 3) & 1;
    const int rA0  = wm * 32 + (lane & 15);
    const int tl   = l7 + (hi16 << 3);

    #pragma unroll
    for (int ks = 0; ks < 4; ks++) {
        uint32_t ah[2][4], al[2][4], bh[3][4], bl[3][4];
        const int kqa = ks * 2 + hi16;
        uint32_t sa = base + OFF_AHI + (uint32_t)rA0 * 128 + (((uint32_t)(kqa ^ l7)) << 4);
        ldsm4(ah[0], sa);
        ldsm4(ah[1], sa + 16 * 128);
        uint32_t sl = sa + (OFF_ALO - OFF_AHI);
        ldsm4(al[0], sl);
        ldsm4(al[1], sl + 16 * 128);
        const int kqb = ks * 2 + cbit;
        #pragma unroll
        for (int j = 0; j < 3; j++) {
            int t = wn * 48 + j * 16 + tl;
            uint32_t sbb = base + OFF_BHI + (uint32_t)t * 128 + (((uint32_t)(kqb ^ l7)) << 4);
            ldsm4(bh[j], sbb);
            ldsm4(bl[j], sbb + (OFF_BLO - OFF_BHI));
        }
        #pragma unroll
        for (int j = 0; j < 3; j++)
            #pragma unroll
            for (int h = 0; h < 2; h++) {
                const uint32_t* bhf = &bh[j][2 * h];
                const uint32_t* blf = &bl[j][2 * h];
                #pragma unroll
                for (int mi = 0; mi < 2; mi++) {
                    mma16816(acc[mi][2 * j + h], ah[mi], bhf);   // hi*hi
                    mma16816(acc[mi][2 * j + h], ah[mi], blf);   // hi*lo
                    mma16816(acc[mi][2 * j + h], al[mi], bhf);   // lo*hi
                }
            }
    }
}

__global__ __launch_bounds__(256, 2)
void gemm_kernel(const float* __restrict__ bias)
{
    extern __shared__ char smem[];
    const uint32_t sb = smem_u32(smem);
    const int tid  = threadIdx.x;
    const int lane = tid & 31;
    const int wid  = tid >> 5;
    const int wm   = wid & 3;
    const int wn   = wid >> 2;
    const int grp  = lane >> 2;
    const int qid  = lane & 3;

    int tiles[2];
    tiles[0] = blockIdx.x;
    tiles[1] = blockIdx.x + GCTA;
    const int nt = (tiles[1] < NTILES) ? 2 : 1;
    const int nw = nt * 3;

    float acc[2][6][4];
    #pragma unroll
    for (int mi = 0; mi < 2; mi++)
        #pragma unroll
        for (int ni = 0; ni < 6; ni++)
            #pragma unroll
            for (int r = 0; r < 4; r++)
                acc[mi][ni][r] = 0.f;

    {
        int t0 = tiles[0];
        fill_chunk(sb,       t0 >> 3, (t0 & 7) * MT, 0, tid); CPA_COMMIT();
        fill_chunk(sb + STG, t0 >> 3, (t0 & 7) * MT, 1, tid); CPA_COMMIT();
    }

    for (int i = 0; i < nw; i++) {
        const int tile = tiles[i / 3];
        const int c    = tile >> 3;
        const int b0   = (tile & 7) * MT;
        const int chk  = i - (i / 3) * 3;

        CPA_WAIT(1);
        __syncthreads();
        mma_chunk(sb + (uint32_t)(i & 1) * STG, wm, wn, lane, acc);

        if (chk == 2) {
            const float* bc = bias + c * T_;
            #pragma unroll
            for (int mi = 0; mi < 2; mi++) {
                const int b = b0 + wm * 32 + mi * 16 + grp;
                float* y0 = g_yT + ((size_t)c * B_ + b) * T_;
                float* y1 = y0 + 8 * T_;
                #pragma unroll
                for (int ni = 0; ni < 6; ni++) {
                    const int t = wn * 48 + ni * 8 + qid * 2;
                    const float bv0 = __ldg(bc + t);
                    const float bv1 = __ldg(bc + t + 1);
                    float2 v0 = { acc[mi][ni][0] + bv0, acc[mi][ni][1] + bv1 };
                    float2 v1 = { acc[mi][ni][2] + bv0, acc[mi][ni][3] + bv1 };
                    *(float2*)(y0 + t) = v0;
                    *(float2*)(y1 + t) = v1;
                    acc[mi][ni][0] = 0.f; acc[mi][ni][1] = 0.f;
                    acc[mi][ni][2] = 0.f; acc[mi][ni][3] = 0.f;
                }
            }
        }
        __syncthreads();
        if (i + 2 < nw) {
            const int j  = i + 2;
            const int jt = tiles[j / 3];
            fill_chunk(sb + (uint32_t)(j & 1) * STG,
                       jt >> 3, (jt & 7) * MT, j - (j / 3) * 3, tid);
        }
        CPA_COMMIT();
    }
}

// ================= T2: yT[C, B*T] -> out[B*T, C], two 64x64 tiles per CTA =================
__global__ __launch_bounds__(256)
void t2_kernel(float* __restrict__ out)
{
    __shared__ float tile0[64 * 69];
    __shared__ float tile1[64 * 69];
    const int bt0 = blockIdx.x * 128;

    float4 va[4], vb[4];
    #pragma unroll
    for (int it = 0; it < 4; it++) {
        int i = threadIdx.x + it * 256;
        int cc = i >> 4, q = i & 15;
        const float* src = &g_yT[(size_t)cc * (B_ * T_) + bt0 + q * 4];
        va[it] = *(const float4*)(src);
        vb[it] = *(const float4*)(src + 64);
    }
    #pragma unroll
    for (int it = 0; it < 4; it++) {
        int i = threadIdx.x + it * 256;
        int cc = i >> 4, q = i & 15;
        float* d0 = &tile0[cc * 69 + q * 4];
        d0[0] = va[it].x; d0[1] = va[it].y; d0[2] = va[it].z; d0[3] = va[it].w;
        float* d1 = &tile1[cc * 69 + q * 4];
        d1[0] = vb[it].x; d1[1] = vb[it].y; d1[2] = vb[it].z; d1[3] = vb[it].w;
    }
    __syncthreads();
    #pragma unroll
    for (int it = 0; it < 4; it++) {
        int i = threadIdx.x + it * 256;
        int r = i >> 4, cq = i & 15;
        float4 v, w;
        v.x = tile0[(cq * 4 + 0) * 69 + r];
        v.y = tile0[(cq * 4 + 1) * 69 + r];
        v.z = tile0[(cq * 4 + 2) * 69 + r];
        v.w = tile0[(cq * 4 + 3) * 69 + r];
        w.x = tile1[(cq * 4 + 0) * 69 + r];
        w.y = tile1[(cq * 4 + 1) * 69 + r];
        w.z = tile1[(cq * 4 + 2) * 69 + r];
        w.w = tile1[(cq * 4 + 3) * 69 + r];
        *(float4*)&out[(size_t)(bt0 + r) * C_ + cq * 4] = v;
        *(float4*)&out[(size_t)(bt0 + 64 + r) * C_ + cq * 4] = w;
    }
}

// ================= launch =================
extern "C" void kernel_launch(void* const* d_in, const int* in_sizes, int n_in,
                              void* d_out, int out_size)
{
    const float* x    = (const float*)d_in[0];  // [B, S, C]
    const float* W    = (const float*)d_in[1];  // [C, O, T]
    const float* bias = (const float*)d_in[2];  // [C, T]
    float* out = (float*)d_out;                 // [B, T, C]

    cudaFuncSetAttribute(gemm_kernel,
                         cudaFuncAttributeMaxDynamicSharedMemorySize, SMEM_TOT);

    t0_kernel<<<C_, 256>>>(W);
    t1_kernel<<<dim3(B_, 2), 256>>>(x);
    gemm_kernel<<<GCTA, 256, SMEM_TOT>>>(bias);
    t2_kernel<<<(B_ * T_) / 128, 256>>>(out);
}

// round 11
// speedup vs baseline: 1.0228x; 1.0228x over previous
#include <cuda_runtime.h>
#include <cuda_bf16.h>
#include <cstdint>

// ---------------- problem constants ----------------
#define B_   1024
#define S_   336
#define C_   64
#define O_   168
#define T_   96
#define O2   192            // K padded to 3 chunks of 64
#define CH   64             // k per chunk
#define NCH  3
#define MT   128            // batches per GEMM tile
#define NTILES 512          // 64 channels x 8 b-tiles
#define GCTA  296           // persistent gemm CTAs (148 SMs x 2)

// ---------------- scratch (device globals; no allocs) ----------------
__device__ __nv_bfloat16 g_xhi[(size_t)C_ * B_ * O2];       // [c][b][o]  (o padded w/ zeros)
__device__ __nv_bfloat16 g_xlo[(size_t)C_ * B_ * O2];
__device__ unsigned char g_bhi[(size_t)C_ * NCH * T_ * 128];// pre-swizzled W hi image
__device__ unsigned char g_blo[(size_t)C_ * NCH * T_ * 128];
__device__ float         g_yT [(size_t)C_ * B_ * T_];       // [c][b][t]

// split f into bf16 hi + bf16 lo (pairwise, packed)
__device__ __forceinline__ void split2(float f0, float f1, uint32_t& h, uint32_t& l)
{
    __nv_bfloat162 hb = __floats2bfloat162_rn(f0, f1);
    float r0 = f0 - __bfloat162float(hb.x);
    float r1 = f1 - __bfloat162float(hb.y);
    __nv_bfloat162 lb = __floats2bfloat162_rn(r0, r1);
    h = *reinterpret_cast<uint32_t*>(&hb);
    l = *reinterpret_cast<uint32_t*>(&lb);
}
__device__ __forceinline__ uint32_t smem_u32(const void* p) {
    uint32_t a;
    asm("{ .reg .u64 t; cvta.to.shared.u64 t, %1; cvt.u32.u64 %0, t; }" : "=r"(a) : "l"(p));
    return a;
}
__device__ __forceinline__ void mma16816(float* d, const uint32_t* a, const uint32_t* b)
{
    asm volatile(
        "mma.sync.aligned.m16n8k16.row.col.f32.bf16.bf16.f32 "
        "{%0,%1,%2,%3}, {%4,%5,%6,%7}, {%8,%9}, {%0,%1,%2,%3};"
        : "+f"(d[0]), "+f"(d[1]), "+f"(d[2]), "+f"(d[3])
        : "r"(a[0]), "r"(a[1]), "r"(a[2]), "r"(a[3]), "r"(b[0]), "r"(b[1]));
}
__device__ __forceinline__ void ldsm4(uint32_t* r, uint32_t addr)
{
    asm volatile("ldmatrix.sync.aligned.m8n8.x4.shared.b16 {%0,%1,%2,%3}, [%4];"
                 : "=r"(r[0]), "=r"(r[1]), "=r"(r[2]), "=r"(r[3]) : "r"(addr));
}
#define CPA16(dst, src) \
    asm volatile("cp.async.cg.shared.global [%0], [%1], 16;" :: "r"(dst), "l"(src))
#define CPA_COMMIT() asm volatile("cp.async.commit_group;" ::: "memory")
#define CPA_WAIT(n)  asm volatile("cp.async.wait_group %0;" :: "n"(n) : "memory")

// ================= T0: W[c][o][t] -> pre-swizzled bf16 hi/lo images (zero padded) =================
__global__ __launch_bounds__(256)
void t0_kernel(const float* __restrict__ W)
{
    const int c = blockIdx.x;
    const float* Wc = W + (size_t)c * (O_ * T_);
    for (int idx = threadIdx.x; idx < 48 * T_; idx += 256) {
        int oq = idx / T_;
        int t  = idx - oq * T_;
        int o  = oq * 4;
        float f0 = (o + 0 < O_) ? Wc[(o + 0) * T_ + t] : 0.f;
        float f1 = (o + 1 < O_) ? Wc[(o + 1) * T_ + t] : 0.f;
        float f2 = (o + 2 < O_) ? Wc[(o + 2) * T_ + t] : 0.f;
        float f3 = (o + 3 < O_) ? Wc[(o + 3) * T_ + t] : 0.f;
        uint2 hv, lv;
        split2(f0, f1, hv.x, lv.x);
        split2(f2, f3, hv.y, lv.y);
        int chunk = o >> 6;
        int kc    = o & 63;
        uint32_t off = (((uint32_t)(c * NCH + chunk) * T_ + t) << 7)
                     + (((uint32_t)(kc >> 3) ^ (t & 7)) << 4) + ((kc >> 2) & 1) * 8;
        *(uint2*)(g_bhi + off) = hv;
        *(uint2*)(g_blo + off) = lv;
    }
}

// ================= T1 (R6-proven): x[B,S,C] -> xT hi/lo [C,B,O2] (zero-padded K) =================
__global__ __launch_bounds__(256)
void t1_kernel(const float* __restrict__ x)
{
    __shared__ float smt[32 * 172];
    const int b    = blockIdx.x;
    const int half = blockIdx.y;
    const uint4* xb = reinterpret_cast<const uint4*>(
        x + (size_t)b * (S_ * C_) + (size_t)(S_ - O_) * C_);

    for (int i = threadIdx.x; i < O_ * 8; i += 256) {
        int o = i >> 3, q = i & 7;
        uint4 v = xb[o * 16 + half * 8 + q];
        float* d = &smt[(q * 4) * 172 + o];
        d[0 * 172] = __uint_as_float(v.x);
        d[1 * 172] = __uint_as_float(v.y);
        d[2 * 172] = __uint_as_float(v.z);
        d[3 * 172] = __uint_as_float(v.w);
    }
    __syncthreads();

    for (int idx = threadIdx.x; idx < 32 * 24; idx += 256) {
        int cl = idx / 24, ch = idx - cl * 24;
        uint4 hw = make_uint4(0, 0, 0, 0), lw = make_uint4(0, 0, 0, 0);
        if (ch < 21) {
            const float* src = &smt[cl * 172 + ch * 8];
            float4 f0 = *(const float4*)(src);
            float4 f1 = *(const float4*)(src + 4);
            split2(f0.x, f0.y, hw.x, lw.x);
            split2(f0.z, f0.w, hw.y, lw.y);
            split2(f1.x, f1.y, hw.z, lw.z);
            split2(f1.z, f1.w, hw.w, lw.w);
        }
        size_t base = ((size_t)(half * 32 + cl) * B_ + b) * O2 + ch * 8;
        *(uint4*)(g_xhi + base) = hw;
        *(uint4*)(g_xlo + base) = lw;
    }
}

// ================= GEMM (R9-proven): persistent CTAs, flattened (tile,chunk) pipeline =================
// stage layout (bytes): A_hi 16K | A_lo 16K | B_hi 12K | B_lo 12K  = 56K; 2 stages = 112K
#define OFF_AHI  0
#define OFF_ALO  16384
#define OFF_BHI  32768
#define OFF_BLO  45056
#define STG      57344
#define SMEM_TOT (2 * STG)

__device__ __forceinline__ void fill_chunk(uint32_t sbase, int c, int b0, int chunk, int tid)
{
    const char* axh = (const char*)g_xhi
        + ((size_t)((c << 10) + b0) * O2 + (size_t)chunk * CH) * 2;
    const char* axl = (const char*)g_xlo
        + ((size_t)((c << 10) + b0) * O2 + (size_t)chunk * CH) * 2;
    #pragma unroll
    for (int it = 0; it < 4; it++) {
        int i = tid + it * 256;
        int r = i >> 3, cq = i & 7;
        uint32_t sw = (uint32_t)r * 128 + (((uint32_t)cq ^ (r & 7)) << 4);
        CPA16(sbase + OFF_AHI + sw, axh + (size_t)r * (O2 * 2) + cq * 16);
        CPA16(sbase + OFF_ALO + sw, axl + (size_t)r * (O2 * 2) + cq * 16);
    }
    const char* bh = (const char*)g_bhi + (size_t)(c * NCH + chunk) * (T_ * 128);
    const char* bl = (const char*)g_blo + (size_t)(c * NCH + chunk) * (T_ * 128);
    #pragma unroll
    for (int it = 0; it < 3; it++) {
        int i = tid + it * 256;
        CPA16(sbase + OFF_BHI + i * 16, bh + (size_t)i * 16);
        CPA16(sbase + OFF_BLO + i * 16, bl + (size_t)i * 16);
    }
}

__device__ __forceinline__ void mma_chunk(uint32_t base, int wm, int wn, int lane,
                                          float (*acc)[6][4])
{
    const int l7   = lane & 7;
    const int hi16 = lane >> 4;
    const int cbit = (lane >> 3) & 1;
    const int rA0  = wm * 32 + (lane & 15);
    const int tl   = l7 + (hi16 << 3);

    #pragma unroll
    for (int ks = 0; ks < 4; ks++) {
        uint32_t ah[2][4], al[2][4], bh[3][4], bl[3][4];
        const int kqa = ks * 2 + hi16;
        uint32_t sa = base + OFF_AHI + (uint32_t)rA0 * 128 + (((uint32_t)(kqa ^ l7)) << 4);
        ldsm4(ah[0], sa);
        ldsm4(ah[1], sa + 16 * 128);
        uint32_t sl = sa + (OFF_ALO - OFF_AHI);
        ldsm4(al[0], sl);
        ldsm4(al[1], sl + 16 * 128);
        const int kqb = ks * 2 + cbit;
        #pragma unroll
        for (int j = 0; j < 3; j++) {
            int t = wn * 48 + j * 16 + tl;
            uint32_t sbb = base + OFF_BHI + (uint32_t)t * 128 + (((uint32_t)(kqb ^ l7)) << 4);
            ldsm4(bh[j], sbb);
            ldsm4(bl[j], sbb + (OFF_BLO - OFF_BHI));
        }
        #pragma unroll
        for (int j = 0; j < 3; j++)
            #pragma unroll
            for (int h = 0; h < 2; h++) {
                const uint32_t* bhf = &bh[j][2 * h];
                const uint32_t* blf = &bl[j][2 * h];
                #pragma unroll
                for (int mi = 0; mi < 2; mi++) {
                    mma16816(acc[mi][2 * j + h], ah[mi], bhf);   // hi*hi
                    mma16816(acc[mi][2 * j + h], ah[mi], blf);   // hi*lo
                    mma16816(acc[mi][2 * j + h], al[mi], bhf);   // lo*hi
                }
            }
    }
}

__global__ __launch_bounds__(256, 2)
void gemm_kernel(const float* __restrict__ bias)
{
    extern __shared__ char smem[];
    const uint32_t sb = smem_u32(smem);
    const int tid  = threadIdx.x;
    const int lane = tid & 31;
    const int wid  = tid >> 5;
    const int wm   = wid & 3;
    const int wn   = wid >> 2;
    const int grp  = lane >> 2;
    const int qid  = lane & 3;

    int tiles[2];
    tiles[0] = blockIdx.x;
    tiles[1] = blockIdx.x + GCTA;
    const int nt = (tiles[1] < NTILES) ? 2 : 1;
    const int nw = nt * 3;

    float acc[2][6][4];
    #pragma unroll
    for (int mi = 0; mi < 2; mi++)
        #pragma unroll
        for (int ni = 0; ni < 6; ni++)
            #pragma unroll
            for (int r = 0; r < 4; r++)
                acc[mi][ni][r] = 0.f;

    {
        int t0 = tiles[0];
        fill_chunk(sb,       t0 >> 3, (t0 & 7) * MT, 0, tid); CPA_COMMIT();
        fill_chunk(sb + STG, t0 >> 3, (t0 & 7) * MT, 1, tid); CPA_COMMIT();
    }

    for (int i = 0; i < nw; i++) {
        const int tile = tiles[i / 3];
        const int c    = tile >> 3;
        const int b0   = (tile & 7) * MT;
        const int chk  = i - (i / 3) * 3;

        CPA_WAIT(1);
        __syncthreads();
        mma_chunk(sb + (uint32_t)(i & 1) * STG, wm, wn, lane, acc);

        if (chk == 2) {
            const float* bc = bias + c * T_;
            #pragma unroll
            for (int mi = 0; mi < 2; mi++) {
                const int b = b0 + wm * 32 + mi * 16 + grp;
                float* y0 = g_yT + ((size_t)c * B_ + b) * T_;
                float* y1 = y0 + 8 * T_;
                #pragma unroll
                for (int ni = 0; ni < 6; ni++) {
                    const int t = wn * 48 + ni * 8 + qid * 2;
                    const float bv0 = __ldg(bc + t);
                    const float bv1 = __ldg(bc + t + 1);
                    float2 v0 = { acc[mi][ni][0] + bv0, acc[mi][ni][1] + bv1 };
                    float2 v1 = { acc[mi][ni][2] + bv0, acc[mi][ni][3] + bv1 };
                    *(float2*)(y0 + t) = v0;
                    *(float2*)(y1 + t) = v1;
                    acc[mi][ni][0] = 0.f; acc[mi][ni][1] = 0.f;
                    acc[mi][ni][2] = 0.f; acc[mi][ni][3] = 0.f;
                }
            }
        }
        __syncthreads();
        if (i + 2 < nw) {
            const int j  = i + 2;
            const int jt = tiles[j / 3];
            fill_chunk(sb + (uint32_t)(j & 1) * STG,
                       jt >> 3, (jt & 7) * MT, j - (j / 3) * 3, tid);
        }
        CPA_COMMIT();
    }
}

// ================= T2 (R6-proven): yT[C, B*T] -> out[B*T, C], 64x64 tiles =================
__global__ __launch_bounds__(256)
void t2_kernel(float* __restrict__ out)
{
    __shared__ float tile[64 * 69];               // pitch 69
    const int bt0 = blockIdx.x * 64;

    #pragma unroll
    for (int i = threadIdx.x; i < 1024; i += 256) {
        int cc = i >> 4, q = i & 15;
        float4 v = *(const float4*)&g_yT[(size_t)cc * (B_ * T_) + bt0 + q * 4];
        float* d = &tile[cc * 69 + q * 4];
        d[0] = v.x; d[1] = v.y; d[2] = v.z; d[3] = v.w;
    }
    __syncthreads();
    #pragma unroll
    for (int i = threadIdx.x; i < 1024; i += 256) {
        int r = i >> 4, cq = i & 15;
        float4 v;
        v.x = tile[(cq * 4 + 0) * 69 + r];
        v.y = tile[(cq * 4 + 1) * 69 + r];
        v.z = tile[(cq * 4 + 2) * 69 + r];
        v.w = tile[(cq * 4 + 3) * 69 + r];
        *(float4*)&out[(size_t)(bt0 + r) * C_ + cq * 4] = v;
    }
}

// ================= launch =================
extern "C" void kernel_launch(void* const* d_in, const int* in_sizes, int n_in,
                              void* d_out, int out_size)
{
    const float* x    = (const float*)d_in[0];  // [B, S, C]
    const float* W    = (const float*)d_in[1];  // [C, O, T]
    const float* bias = (const float*)d_in[2];  // [C, T]
    float* out = (float*)d_out;                 // [B, T, C]

    cudaFuncSetAttribute(gemm_kernel,
                         cudaFuncAttributeMaxDynamicSharedMemorySize, SMEM_TOT);

    t0_kernel<<<C_, 256>>>(W);
    t1_kernel<<<dim3(B_, 2), 256>>>(x);
    gemm_kernel<<<GCTA, 256, SMEM_TOT>>>(bias);
    t2_kernel<<<(B_ * T_) / 64, 256>>>(out);
}

// round 12
// speedup vs baseline: 1.2989x; 1.2700x over previous
#include <cuda_runtime.h>
#include <cuda_fp16.h>
#include <cstdint>

// ---------------- problem constants ----------------
#define B_   1024
#define S_   336
#define C_   64
#define O_   168
#define T_   96
#define O2   192            // K padded to 3 chunks of 64
#define CH   64             // k per chunk
#define NCH  3
#define MT   128            // batches per GEMM tile
#define NTILES 512          // 64 channels x 8 b-tiles
#define GCTA  296           // persistent gemm CTAs (148 SMs x 2)

// ---------------- scratch (device globals; no allocs) ----------------
__device__ __half         g_x [(size_t)C_ * B_ * O2];       // [c][b][o]  fp16, zero-padded K
__device__ unsigned char  g_w [(size_t)C_ * NCH * T_ * 128];// pre-swizzled fp16 W image
__device__ float          g_yT[(size_t)C_ * B_ * T_];       // [c][b][t]

__device__ __forceinline__ uint32_t packh(float a, float b)
{
    __half2 h = __floats2half2_rn(a, b);
    return *reinterpret_cast<uint32_t*>(&h);
}
__device__ __forceinline__ uint32_t smem_u32(const void* p) {
    uint32_t a;
    asm("{ .reg .u64 t; cvta.to.shared.u64 t, %1; cvt.u32.u64 %0, t; }" : "=r"(a) : "l"(p));
    return a;
}
__device__ __forceinline__ void mma16816(float* d, const uint32_t* a, const uint32_t* b)
{
    asm volatile(
        "mma.sync.aligned.m16n8k16.row.col.f32.f16.f16.f32 "
        "{%0,%1,%2,%3}, {%4,%5,%6,%7}, {%8,%9}, {%0,%1,%2,%3};"
        : "+f"(d[0]), "+f"(d[1]), "+f"(d[2]), "+f"(d[3])
        : "r"(a[0]), "r"(a[1]), "r"(a[2]), "r"(a[3]), "r"(b[0]), "r"(b[1]));
}
__device__ __forceinline__ void ldsm4(uint32_t* r, uint32_t addr)
{
    asm volatile("ldmatrix.sync.aligned.m8n8.x4.shared.b16 {%0,%1,%2,%3}, [%4];"
                 : "=r"(r[0]), "=r"(r[1]), "=r"(r[2]), "=r"(r[3]) : "r"(addr));
}
#define CPA16(dst, src) \
    asm volatile("cp.async.cg.shared.global [%0], [%1], 16;" :: "r"(dst), "l"(src))
#define CPA_COMMIT() asm volatile("cp.async.commit_group;" ::: "memory")
#define CPA_WAIT(n)  asm volatile("cp.async.wait_group %0;" :: "n"(n) : "memory")

// ================= T0: W[c][o][t] -> pre-swizzled fp16 image (zero padded) =================
__global__ __launch_bounds__(256)
void t0_kernel(const float* __restrict__ W)
{
    const int c = blockIdx.x;
    const float* Wc = W + (size_t)c * (O_ * T_);
    for (int idx = threadIdx.x; idx < 48 * T_; idx += 256) {
        int oq = idx / T_;
        int t  = idx - oq * T_;
        int o  = oq * 4;
        float f0 = (o + 0 < O_) ? Wc[(o + 0) * T_ + t] : 0.f;
        float f1 = (o + 1 < O_) ? Wc[(o + 1) * T_ + t] : 0.f;
        float f2 = (o + 2 < O_) ? Wc[(o + 2) * T_ + t] : 0.f;
        float f3 = (o + 3 < O_) ? Wc[(o + 3) * T_ + t] : 0.f;
        uint2 hv;
        hv.x = packh(f0, f1);
        hv.y = packh(f2, f3);
        int chunk = o >> 6;
        int kc    = o & 63;
        uint32_t off = (((uint32_t)(c * NCH + chunk) * T_ + t) << 7)
                     + (((uint32_t)(kc >> 3) ^ (t & 7)) << 4) + ((kc >> 2) & 1) * 8;
        *(uint2*)(g_w + off) = hv;
    }
}

// ================= T1: x[B,S,C] -> xT fp16 [C,B,O2] (zero-padded K) =================
__global__ __launch_bounds__(256)
void t1_kernel(const float* __restrict__ x)
{
    __shared__ float smt[32 * 172];
    const int b    = blockIdx.x;
    const int half = blockIdx.y;
    const uint4* xb = reinterpret_cast<const uint4*>(
        x + (size_t)b * (S_ * C_) + (size_t)(S_ - O_) * C_);

    for (int i = threadIdx.x; i < O_ * 8; i += 256) {
        int o = i >> 3, q = i & 7;
        uint4 v = xb[o * 16 + half * 8 + q];
        float* d = &smt[(q * 4) * 172 + o];
        d[0 * 172] = __uint_as_float(v.x);
        d[1 * 172] = __uint_as_float(v.y);
        d[2 * 172] = __uint_as_float(v.z);
        d[3 * 172] = __uint_as_float(v.w);
    }
    __syncthreads();

    for (int idx = threadIdx.x; idx < 32 * 24; idx += 256) {
        int cl = idx / 24, ch = idx - cl * 24;
        uint4 hw = make_uint4(0, 0, 0, 0);
        if (ch < 21) {
            const float* src = &smt[cl * 172 + ch * 8];
            float4 f0 = *(const float4*)(src);
            float4 f1 = *(const float4*)(src + 4);
            hw.x = packh(f0.x, f0.y);
            hw.y = packh(f0.z, f0.w);
            hw.z = packh(f1.x, f1.y);
            hw.w = packh(f1.z, f1.w);
        }
        size_t base = ((size_t)(half * 32 + cl) * B_ + b) * O2 + ch * 8;
        *(uint4*)(g_x + base) = hw;
    }
}

// ================= GEMM: persistent CTAs, flattened (tile,chunk) cp.async pipeline =================
// stage layout (bytes): A 16K | B 12K = 28K; 2 stages = 56K
#define OFF_A   0
#define OFF_B   16384
#define STG     28672
#define SMEM_TOT (2 * STG)

__device__ __forceinline__ void fill_chunk(uint32_t sbase, int c, int b0, int chunk, int tid)
{
    const char* ax = (const char*)g_x
        + ((size_t)((c << 10) + b0) * O2 + (size_t)chunk * CH) * 2;
    #pragma unroll
    for (int it = 0; it < 4; it++) {
        int i = tid + it * 256;
        int r = i >> 3, cq = i & 7;
        uint32_t sw = (uint32_t)r * 128 + (((uint32_t)cq ^ (r & 7)) << 4);
        CPA16(sbase + OFF_A + sw, ax + (size_t)r * (O2 * 2) + cq * 16);
    }
    const char* bw = (const char*)g_w + (size_t)(c * NCH + chunk) * (T_ * 128);
    #pragma unroll
    for (int it = 0; it < 3; it++) {
        int i = tid + it * 256;
        CPA16(sbase + OFF_B + i * 16, bw + (size_t)i * 16);
    }
}

__device__ __forceinline__ void mma_chunk(uint32_t base, int wm, int wn, int lane,
                                          float (*acc)[6][4])
{
    const int l7   = lane & 7;
    const int hi16 = lane >> 4;
    const int cbit = (lane >> 3) & 1;
    const int rA0  = wm * 32 + (lane & 15);
    const int tl   = l7 + (hi16 << 3);

    #pragma unroll
    for (int ks = 0; ks < 4; ks++) {
        uint32_t a[2][4], b[3][4];
        const int kqa = ks * 2 + hi16;
        uint32_t sa = base + OFF_A + (uint32_t)rA0 * 128 + (((uint32_t)(kqa ^ l7)) << 4);
        ldsm4(a[0], sa);
        ldsm4(a[1], sa + 16 * 128);
        const int kqb = ks * 2 + cbit;
        #pragma unroll
        for (int j = 0; j < 3; j++) {
            int t = wn * 48 + j * 16 + tl;
            uint32_t sbb = base + OFF_B + (uint32_t)t * 128 + (((uint32_t)(kqb ^ l7)) << 4);
            ldsm4(b[j], sbb);
        }
        #pragma unroll
        for (int j = 0; j < 3; j++)
            #pragma unroll
            for (int h = 0; h < 2; h++) {
                const uint32_t* bf = &b[j][2 * h];
                #pragma unroll
                for (int mi = 0; mi < 2; mi++)
                    mma16816(acc[mi][2 * j + h], a[mi], bf);
            }
    }
}

__global__ __launch_bounds__(256, 2)
void gemm_kernel(const float* __restrict__ bias)
{
    extern __shared__ char smem[];
    const uint32_t sb = smem_u32(smem);
    const int tid  = threadIdx.x;
    const int lane = tid & 31;
    const int wid  = tid >> 5;
    const int wm   = wid & 3;
    const int wn   = wid >> 2;
    const int grp  = lane >> 2;
    const int qid  = lane & 3;

    int tiles[2];
    tiles[0] = blockIdx.x;
    tiles[1] = blockIdx.x + GCTA;
    const int nt = (tiles[1] < NTILES) ? 2 : 1;
    const int nw = nt * 3;

    float acc[2][6][4];
    #pragma unroll
    for (int mi = 0; mi < 2; mi++)
        #pragma unroll
        for (int ni = 0; ni < 6; ni++)
            #pragma unroll
            for (int r = 0; r < 4; r++)
                acc[mi][ni][r] = 0.f;

    {
        int t0 = tiles[0];
        fill_chunk(sb,       t0 >> 3, (t0 & 7) * MT, 0, tid); CPA_COMMIT();
        fill_chunk(sb + STG, t0 >> 3, (t0 & 7) * MT, 1, tid); CPA_COMMIT();
    }

    for (int i = 0; i < nw; i++) {
        const int tile = tiles[i / 3];
        const int c    = tile >> 3;
        const int b0   = (tile & 7) * MT;
        const int chk  = i - (i / 3) * 3;

        CPA_WAIT(1);
        __syncthreads();
        mma_chunk(sb + (uint32_t)(i & 1) * STG, wm, wn, lane, acc);

        if (chk == 2) {
            const float* bc = bias + c * T_;
            #pragma unroll
            for (int mi = 0; mi < 2; mi++) {
                const int b = b0 + wm * 32 + mi * 16 + grp;
                float* y0 = g_yT + ((size_t)c * B_ + b) * T_;
                float* y1 = y0 + 8 * T_;
                #pragma unroll
                for (int ni = 0; ni < 6; ni++) {
                    const int t = wn * 48 + ni * 8 + qid * 2;
                    const float bv0 = __ldg(bc + t);
                    const float bv1 = __ldg(bc + t + 1);
                    float2 v0 = { acc[mi][ni][0] + bv0, acc[mi][ni][1] + bv1 };
                    float2 v1 = { acc[mi][ni][2] + bv0, acc[mi][ni][3] + bv1 };
                    *(float2*)(y0 + t) = v0;
                    *(float2*)(y1 + t) = v1;
                    acc[mi][ni][0] = 0.f; acc[mi][ni][1] = 0.f;
                    acc[mi][ni][2] = 0.f; acc[mi][ni][3] = 0.f;
                }
            }
        }
        __syncthreads();
        if (i + 2 < nw) {
            const int j  = i + 2;
            const int jt = tiles[j / 3];
            fill_chunk(sb + (uint32_t)(j & 1) * STG,
                       jt >> 3, (jt & 7) * MT, j - (j / 3) * 3, tid);
        }
        CPA_COMMIT();
    }
}

// ================= T2 (R6-proven): yT[C, B*T] -> out[B*T, C], 64x64 tiles =================
__global__ __launch_bounds__(256)
void t2_kernel(float* __restrict__ out)
{
    __shared__ float tile[64 * 69];               // pitch 69
    const int bt0 = blockIdx.x * 64;

    #pragma unroll
    for (int i = threadIdx.x; i < 1024; i += 256) {
        int cc = i >> 4, q = i & 15;
        float4 v = *(const float4*)&g_yT[(size_t)cc * (B_ * T_) + bt0 + q * 4];
        float* d = &tile[cc * 69 + q * 4];
        d[0] = v.x; d[1] = v.y; d[2] = v.z; d[3] = v.w;
    }
    __syncthreads();
    #pragma unroll
    for (int i = threadIdx.x; i < 1024; i += 256) {
        int r = i >> 4, cq = i & 15;
        float4 v;
        v.x = tile[(cq * 4 + 0) * 69 + r];
        v.y = tile[(cq * 4 + 1) * 69 + r];
        v.z = tile[(cq * 4 + 2) * 69 + r];
        v.w = tile[(cq * 4 + 3) * 69 + r];
        *(float4*)&out[(size_t)(bt0 + r) * C_ + cq * 4] = v;
    }
}

// ================= launch =================
extern "C" void kernel_launch(void* const* d_in, const int* in_sizes, int n_in,
                              void* d_out, int out_size)
{
    const float* x    = (const float*)d_in[0];  // [B, S, C]
    const float* W    = (const float*)d_in[1];  // [C, O, T]
    const float* bias = (const float*)d_in[2];  // [C, T]
    float* out = (float*)d_out;                 // [B, T, C]

    cudaFuncSetAttribute(gemm_kernel,
                         cudaFuncAttributeMaxDynamicSharedMemorySize, SMEM_TOT);

    t0_kernel<<<C_, 256>>>(W);
    t1_kernel<<<dim3(B_, 2), 256>>>(x);
    gemm_kernel<<<GCTA, 256, SMEM_TOT>>>(bias);
    t2_kernel<<<(B_ * T_) / 64, 256>>>(out);
}

// round 13
// speedup vs baseline: 1.3880x; 1.0686x over previous
#include <cuda_runtime.h>
#include <cuda_fp16.h>
#include <cstdint>

// ---------------- problem constants ----------------
#define B_   1024
#define S_   336
#define C_   64
#define O_   168
#define T_   96
#define O2   192            // K padded to 3 chunks of 64
#define CH   64             // k per chunk
#define NCH  3
#define MT   128            // batches per GEMM tile
#define NTILES 512          // 64 channels x 8 b-tiles
#define GCTA  296           // persistent gemm CTAs (148 SMs x 2)

// ---------------- scratch (device globals; no allocs) ----------------
__device__ __half         g_x [(size_t)C_ * B_ * O2];       // [c][b][o]  fp16, zero-padded K
__device__ unsigned char  g_w [(size_t)C_ * NCH * T_ * 128];// pre-swizzled fp16 W image
__device__ __half         g_yT[(size_t)C_ * B_ * T_];       // [c][b][t]  fp16

__device__ __forceinline__ uint32_t packh(float a, float b)
{
    __half2 h = __floats2half2_rn(a, b);
    return *reinterpret_cast<uint32_t*>(&h);
}
__device__ __forceinline__ uint32_t smem_u32(const void* p) {
    uint32_t a;
    asm("{ .reg .u64 t; cvta.to.shared.u64 t, %1; cvt.u32.u64 %0, t; }" : "=r"(a) : "l"(p));
    return a;
}
__device__ __forceinline__ void mma16816(float* d, const uint32_t* a, const uint32_t* b)
{
    asm volatile(
        "mma.sync.aligned.m16n8k16.row.col.f32.f16.f16.f32 "
        "{%0,%1,%2,%3}, {%4,%5,%6,%7}, {%8,%9}, {%0,%1,%2,%3};"
        : "+f"(d[0]), "+f"(d[1]), "+f"(d[2]), "+f"(d[3])
        : "r"(a[0]), "r"(a[1]), "r"(a[2]), "r"(a[3]), "r"(b[0]), "r"(b[1]));
}
__device__ __forceinline__ void ldsm4(uint32_t* r, uint32_t addr)
{
    asm volatile("ldmatrix.sync.aligned.m8n8.x4.shared.b16 {%0,%1,%2,%3}, [%4];"
                 : "=r"(r[0]), "=r"(r[1]), "=r"(r[2]), "=r"(r[3]) : "r"(addr));
}
#define CPA16(dst, src) \
    asm volatile("cp.async.cg.shared.global [%0], [%1], 16;" :: "r"(dst), "l"(src))
#define CPA_COMMIT() asm volatile("cp.async.commit_group;" ::: "memory")
#define CPA_WAIT(n)  asm volatile("cp.async.wait_group %0;" :: "n"(n) : "memory")

// ================= T0: W[c][o][t] -> pre-swizzled fp16 image (zero padded) =================
__global__ __launch_bounds__(256)
void t0_kernel(const float* __restrict__ W)
{
    const int c = blockIdx.x;
    const float* Wc = W + (size_t)c * (O_ * T_);
    for (int idx = threadIdx.x; idx < 48 * T_; idx += 256) {
        int oq = idx / T_;
        int t  = idx - oq * T_;
        int o  = oq * 4;
        float f0 = (o + 0 < O_) ? Wc[(o + 0) * T_ + t] : 0.f;
        float f1 = (o + 1 < O_) ? Wc[(o + 1) * T_ + t] : 0.f;
        float f2 = (o + 2 < O_) ? Wc[(o + 2) * T_ + t] : 0.f;
        float f3 = (o + 3 < O_) ? Wc[(o + 3) * T_ + t] : 0.f;
        uint2 hv;
        hv.x = packh(f0, f1);
        hv.y = packh(f2, f3);
        int chunk = o >> 6;
        int kc    = o & 63;
        uint32_t off = (((uint32_t)(c * NCH + chunk) * T_ + t) << 7)
                     + (((uint32_t)(kc >> 3) ^ (t & 7)) << 4) + ((kc >> 2) & 1) * 8;
        *(uint2*)(g_w + off) = hv;
    }
}

// ================= T1: x[B,S,C] -> xT fp16 [C,B,O2] (zero-padded K) =================
__global__ __launch_bounds__(256)
void t1_kernel(const float* __restrict__ x)
{
    __shared__ float smt[32 * 172];
    const int b    = blockIdx.x;
    const int half = blockIdx.y;
    const uint4* xb = reinterpret_cast<const uint4*>(
        x + (size_t)b * (S_ * C_) + (size_t)(S_ - O_) * C_);

    for (int i = threadIdx.x; i < O_ * 8; i += 256) {
        int o = i >> 3, q = i & 7;
        uint4 v = xb[o * 16 + half * 8 + q];
        float* d = &smt[(q * 4) * 172 + o];
        d[0 * 172] = __uint_as_float(v.x);
        d[1 * 172] = __uint_as_float(v.y);
        d[2 * 172] = __uint_as_float(v.z);
        d[3 * 172] = __uint_as_float(v.w);
    }
    __syncthreads();

    for (int idx = threadIdx.x; idx < 32 * 24; idx += 256) {
        int cl = idx / 24, ch = idx - cl * 24;
        uint4 hw = make_uint4(0, 0, 0, 0);
        if (ch < 21) {
            const float* src = &smt[cl * 172 + ch * 8];
            float4 f0 = *(const float4*)(src);
            float4 f1 = *(const float4*)(src + 4);
            hw.x = packh(f0.x, f0.y);
            hw.y = packh(f0.z, f0.w);
            hw.z = packh(f1.x, f1.y);
            hw.w = packh(f1.z, f1.w);
        }
        size_t base = ((size_t)(half * 32 + cl) * B_ + b) * O2 + ch * 8;
        *(uint4*)(g_x + base) = hw;
    }
}

// ================= GEMM: persistent CTAs, flattened (tile,chunk) cp.async pipeline =================
// stage layout (bytes): A 16K | B 12K = 28K; 2 stages = 56K
#define OFF_A   0
#define OFF_B   16384
#define STG     28672
#define SMEM_TOT (2 * STG)

__device__ __forceinline__ void fill_chunk(uint32_t sbase, int c, int b0, int chunk, int tid)
{
    const char* ax = (const char*)g_x
        + ((size_t)((c << 10) + b0) * O2 + (size_t)chunk * CH) * 2;
    #pragma unroll
    for (int it = 0; it < 4; it++) {
        int i = tid + it * 256;
        int r = i >> 3, cq = i & 7;
        uint32_t sw = (uint32_t)r * 128 + (((uint32_t)cq ^ (r & 7)) << 4);
        CPA16(sbase + OFF_A + sw, ax + (size_t)r * (O2 * 2) + cq * 16);
    }
    const char* bw = (const char*)g_w + (size_t)(c * NCH + chunk) * (T_ * 128);
    #pragma unroll
    for (int it = 0; it < 3; it++) {
        int i = tid + it * 256;
        CPA16(sbase + OFF_B + i * 16, bw + (size_t)i * 16);
    }
}

__device__ __forceinline__ void mma_chunk(uint32_t base, int wm, int wn, int lane,
                                          float (*acc)[6][4])
{
    const int l7   = lane & 7;
    const int hi16 = lane >> 4;
    const int cbit = (lane >> 3) & 1;
    const int rA0  = wm * 32 + (lane & 15);
    const int tl   = l7 + (hi16 << 3);

    #pragma unroll
    for (int ks = 0; ks < 4; ks++) {
        uint32_t a[2][4], b[3][4];
        const int kqa = ks * 2 + hi16;
        uint32_t sa = base + OFF_A + (uint32_t)rA0 * 128 + (((uint32_t)(kqa ^ l7)) << 4);
        ldsm4(a[0], sa);
        ldsm4(a[1], sa + 16 * 128);
        const int kqb = ks * 2 + cbit;
        #pragma unroll
        for (int j = 0; j < 3; j++) {
            int t = wn * 48 + j * 16 + tl;
            uint32_t sbb = base + OFF_B + (uint32_t)t * 128 + (((uint32_t)(kqb ^ l7)) << 4);
            ldsm4(b[j], sbb);
        }
        #pragma unroll
        for (int j = 0; j < 3; j++)
            #pragma unroll
            for (int h = 0; h < 2; h++) {
                const uint32_t* bf = &b[j][2 * h];
                #pragma unroll
                for (int mi = 0; mi < 2; mi++)
                    mma16816(acc[mi][2 * j + h], a[mi], bf);
            }
    }
}

__global__ __launch_bounds__(256, 2)
void gemm_kernel(const float* __restrict__ bias)
{
    extern __shared__ char smem[];
    const uint32_t sb = smem_u32(smem);
    const int tid  = threadIdx.x;
    const int lane = tid & 31;
    const int wid  = tid >> 5;
    const int wm   = wid & 3;
    const int wn   = wid >> 2;
    const int grp  = lane >> 2;
    const int qid  = lane & 3;

    int tiles[2];
    tiles[0] = blockIdx.x;
    tiles[1] = blockIdx.x + GCTA;
    const int nt = (tiles[1] < NTILES) ? 2 : 1;
    const int nw = nt * 3;

    float acc[2][6][4];
    #pragma unroll
    for (int mi = 0; mi < 2; mi++)
        #pragma unroll
        for (int ni = 0; ni < 6; ni++)
            #pragma unroll
            for (int r = 0; r < 4; r++)
                acc[mi][ni][r] = 0.f;

    {
        int t0 = tiles[0];
        fill_chunk(sb,       t0 >> 3, (t0 & 7) * MT, 0, tid); CPA_COMMIT();
        fill_chunk(sb + STG, t0 >> 3, (t0 & 7) * MT, 1, tid); CPA_COMMIT();
    }

    for (int i = 0; i < nw; i++) {
        const int tile = tiles[i / 3];
        const int c    = tile >> 3;
        const int b0   = (tile & 7) * MT;
        const int chk  = i - (i / 3) * 3;

        CPA_WAIT(1);
        __syncthreads();
        mma_chunk(sb + (uint32_t)(i & 1) * STG, wm, wn, lane, acc);

        if (chk == 2) {
            const float* bc = bias + c * T_;
            #pragma unroll
            for (int mi = 0; mi < 2; mi++) {
                const int b = b0 + wm * 32 + mi * 16 + grp;
                __half* y0 = g_yT + ((size_t)c * B_ + b) * T_;
                __half* y1 = y0 + 8 * T_;
                #pragma unroll
                for (int ni = 0; ni < 6; ni++) {
                    const int t = wn * 48 + ni * 8 + qid * 2;
                    const float bv0 = __ldg(bc + t);
                    const float bv1 = __ldg(bc + t + 1);
                    uint32_t p0 = packh(acc[mi][ni][0] + bv0, acc[mi][ni][1] + bv1);
                    uint32_t p1 = packh(acc[mi][ni][2] + bv0, acc[mi][ni][3] + bv1);
                    *(uint32_t*)(y0 + t) = p0;
                    *(uint32_t*)(y1 + t) = p1;
                    acc[mi][ni][0] = 0.f; acc[mi][ni][1] = 0.f;
                    acc[mi][ni][2] = 0.f; acc[mi][ni][3] = 0.f;
                }
            }
        }
        __syncthreads();
        if (i + 2 < nw) {
            const int j  = i + 2;
            const int jt = tiles[j / 3];
            fill_chunk(sb + (uint32_t)(j & 1) * STG,
                       jt >> 3, (jt & 7) * MT, j - (j / 3) * 3, tid);
        }
        CPA_COMMIT();
    }
}

// ================= T2: yT fp16 [C, B*T] -> out fp32 [B*T, C], 64x64 tiles =================
__global__ __launch_bounds__(256)
void t2_kernel(float* __restrict__ out)
{
    __shared__ float tile[64 * 69];               // pitch 69
    const int bt0 = blockIdx.x * 64;

    // load 64c x 64bt fp16 (8 halves per thread-item), convert, store fp32 smem
    #pragma unroll
    for (int i = threadIdx.x; i < 512; i += 256) {
        int cc = i >> 3, q = i & 7;
        uint4 v = *(const uint4*)&g_yT[(size_t)cc * (B_ * T_) + bt0 + q * 8];
        const __half2* hp = reinterpret_cast<const __half2*>(&v);
        float* d = &tile[cc * 69 + q * 8];
        #pragma unroll
        for (int k = 0; k < 4; k++) {
            float2 f = __half22float2(hp[k]);
            d[2 * k + 0] = f.x;
            d[2 * k + 1] = f.y;
        }
    }
    __syncthreads();
    #pragma unroll
    for (int i = threadIdx.x; i < 1024; i += 256) {
        int r = i >> 4, cq = i & 15;
        float4 v;
        v.x = tile[(cq * 4 + 0) * 69 + r];
        v.y = tile[(cq * 4 + 1) * 69 + r];
        v.z = tile[(cq * 4 + 2) * 69 + r];
        v.w = tile[(cq * 4 + 3) * 69 + r];
        *(float4*)&out[(size_t)(bt0 + r) * C_ + cq * 4] = v;
    }
}

// ================= launch =================
extern "C" void kernel_launch(void* const* d_in, const int* in_sizes, int n_in,
                              void* d_out, int out_size)
{
    const float* x    = (const float*)d_in[0];  // [B, S, C]
    const float* W    = (const float*)d_in[1];  // [C, O, T]
    const float* bias = (const float*)d_in[2];  // [C, T]
    float* out = (float*)d_out;                 // [B, T, C]

    cudaFuncSetAttribute(gemm_kernel,
                         cudaFuncAttributeMaxDynamicSharedMemorySize, SMEM_TOT);

    t0_kernel<<<C_, 256>>>(W);
    t1_kernel<<<dim3(B_, 2), 256>>>(x);
    gemm_kernel<<<GCTA, 256, SMEM_TOT>>>(bias);
    t2_kernel<<<(B_ * T_) / 64, 256>>>(out);
}